// round 7
// baseline (speedup 1.0000x reference)
#include <cuda_runtime.h>

// CANN recurrent net as a 15-node CUDA graph with Programmatic Dependent Launch.
//   step t: y = J @ s_{t-1};  U = y/recSum_{t-1} + Iext;  s_t = (0.2 U)^2
//   (recSum_{t-1} = K*sum(s_{t-1}) recomputed deterministically by every block)
//   finalize: recSum_14, r_14 = s_14/recSum_14
//
// step_kernel: 420 blocks x 128 threads (1 warp = 1 row, 4*420 = 1680 exactly).
// J rows prefetched to registers BEFORE griddepcontrol.wait; launch_dependents
// issued at kernel entry so successor CTAs (2 spare slots/SM) prefetch while
// the predecessor runs. Dependent work after wait: 6.7KB s stage + dot + store.

#define Nn     1680
#define NBLK   420
#define TPB    128          // 4 warps
#define NWARP  4
#define ITERS  14
#define KC     0.005f

__device__ float g_s[2][Nn];   // unnormalized s vectors, parity-buffered

__device__ __forceinline__ void pdl_wait() {
    asm volatile("griddepcontrol.wait;" ::: "memory");
}
__device__ __forceinline__ void pdl_launch_dependents() {
    asm volatile("griddepcontrol.launch_dependents;" ::: "memory");
}
__device__ __forceinline__ float4 ldcg4(const float4* p) {
    float4 v;
    asm volatile("ld.global.cg.v4.f32 {%0,%1,%2,%3}, [%4];"
                 : "=f"(v.x), "=f"(v.y), "=f"(v.z), "=f"(v.w) : "l"(p));
    return v;
}

__global__ void __launch_bounds__(TPB, 3)
step_kernel(const float* __restrict__ net_in,
            const float* __restrict__ J,
            float* __restrict__ out,
            int t)
{
    __shared__ __align__(16) float s_sm[Nn];
    __shared__ float s_part[NWARP];

    // Release the successor's launch gate immediately: its CTAs can begin
    // their (input-independent) J prefetch while we are still working.
    pdl_launch_dependents();

    const int tid  = threadIdx.x;
    const int lane = tid & 31;
    const int wid  = tid >> 5;
    const int row  = wid * NBLK + blockIdx.x;   // exact cover: 4*420 = 1680

    // ---- prefetch (independent of predecessor): J row -> regs, Iext ----
    const float iext = __ldg(&net_in[row]);
    float4 Jr[14];
    {
        const float4* Jp = reinterpret_cast<const float4*>(J + (size_t)row * Nn);
        #pragma unroll
        for (int j = 0; j < 13; ++j) Jr[j] = __ldg(&Jp[j * 32 + lane]);
        Jr[13] = (lane < 4) ? __ldg(&Jp[416 + lane]) : make_float4(0.f,0.f,0.f,0.f);
    }

    pdl_wait();                // predecessor's g_s writes now visible

    // ---- stage s_{t-1} into smem + deterministic sum (identical everywhere) ----
    const float4* src = (t == 1)
        ? reinterpret_cast<const float4*>(net_in + Nn)
        : reinterpret_cast<const float4*>(g_s[(t - 1) & 1]);
    float rsT = 0.f;
    #pragma unroll
    for (int k = 0; k < 4; ++k) {
        int i = tid + k * TPB;
        if (i < Nn / 4) {
            float4 v = (t == 1) ? __ldg(&src[i]) : ldcg4(&src[i]);
            reinterpret_cast<float4*>(s_sm)[i] = v;
            rsT += (v.x + v.y) + (v.z + v.w);
        }
    }
    #pragma unroll
    for (int o = 16; o; o >>= 1) rsT += __shfl_xor_sync(0xffffffffu, rsT, o);
    if (lane == 0) s_part[wid] = rsT;
    __syncthreads();
    const float rsum = (s_part[0] + s_part[1]) + (s_part[2] + s_part[3]);
    const float invDen = (t == 1) ? 1.0f : 1.0f / (KC * rsum);

    // ---- matvec (register J row x smem s), publish ----
    {
        const float4* s4 = reinterpret_cast<const float4*>(s_sm);
        float a0 = 0.f, a1 = 0.f;
        #pragma unroll
        for (int j = 0; j < 13; ++j) {
            float4 b = s4[j * 32 + lane];
            if (j & 1) {
                a1 = fmaf(Jr[j].x, b.x, a1); a1 = fmaf(Jr[j].y, b.y, a1);
                a1 = fmaf(Jr[j].z, b.z, a1); a1 = fmaf(Jr[j].w, b.w, a1);
            } else {
                a0 = fmaf(Jr[j].x, b.x, a0); a0 = fmaf(Jr[j].y, b.y, a0);
                a0 = fmaf(Jr[j].z, b.z, a0); a0 = fmaf(Jr[j].w, b.w, a0);
            }
        }
        if (lane < 4) {
            float4 b = s4[416 + lane];
            a1 = fmaf(Jr[13].x, b.x, a1); a1 = fmaf(Jr[13].y, b.y, a1);
            a1 = fmaf(Jr[13].z, b.z, a1); a1 = fmaf(Jr[13].w, b.w, a1);
        }
        float acc = a0 + a1;
        #pragma unroll
        for (int o = 16; o; o >>= 1) acc += __shfl_xor_sync(0xffffffffu, acc, o);
        if (lane == 0) {
            float U  = fmaf(acc, invDen, iext);
            float u2 = 0.2f * U;
            float sv = u2 * u2;
            g_s[t & 1][row] = sv;
            if (t == ITERS) out[row] = U;    // U_14
        }
    }
}

__global__ void __launch_bounds__(448)
final_kernel(float* __restrict__ out)
{
    __shared__ float s_part[14];
    const int tid = threadIdx.x, lane = tid & 31, wid = tid >> 5;

    pdl_wait();

    const float4* s4 = reinterpret_cast<const float4*>(g_s[ITERS & 1]);
    const bool has = tid < Nn / 4;     // 420 of 448 threads carry a float4
    float4 a = make_float4(0.f, 0.f, 0.f, 0.f);
    if (has) a = ldcg4(&s4[tid]);
    float v = (a.x + a.y) + (a.z + a.w);
    #pragma unroll
    for (int o = 16; o; o >>= 1) v += __shfl_xor_sync(0xffffffffu, v, o);
    if (lane == 0) s_part[wid] = v;
    __syncthreads();
    float rsum = 0.f;
    #pragma unroll
    for (int w = 0; w < 14; ++w) rsum += s_part[w];
    const float recS = KC * rsum;

    if (tid == 0) out[Nn] = recS;                       // recSum_14
    if (has) {                                          // r_14
        out[Nn + 1 + 4 * tid + 0] = a.x / recS;
        out[Nn + 1 + 4 * tid + 1] = a.y / recS;
        out[Nn + 1 + 4 * tid + 2] = a.z / recS;
        out[Nn + 1 + 4 * tid + 3] = a.w / recS;
    }
}

extern "C" void kernel_launch(void* const* d_in, const int* in_sizes, int n_in,
                              void* d_out, int out_size)
{
    const float* a = (const float*)d_in[0];
    const float* b = (const float*)d_in[1];
    const float* net_in = a;
    const float* J      = b;
    if (n_in >= 2 && in_sizes[0] > in_sizes[1]) { net_in = b; J = a; }
    float* out = (float*)d_out;

    cudaLaunchAttribute attr[1];
    attr[0].id = cudaLaunchAttributeProgrammaticStreamSerialization;
    attr[0].val.programmaticStreamSerializationAllowed = 1;

    cudaLaunchConfig_t cfg = {};
    cfg.gridDim  = dim3(NBLK, 1, 1);
    cfg.blockDim = dim3(TPB, 1, 1);
    cfg.dynamicSmemBytes = 0;
    cfg.stream = 0;            // legacy default stream (captured by harness)
    cfg.attrs = attr;
    cfg.numAttrs = 1;

    for (int t = 1; t <= ITERS; ++t)
        cudaLaunchKernelEx(&cfg, step_kernel, net_in, J, out, t);

    cudaLaunchConfig_t cfgF = cfg;
    cfgF.gridDim  = dim3(1, 1, 1);
    cfgF.blockDim = dim3(448, 1, 1);
    cudaLaunchKernelEx(&cfgF, final_kernel, out);
}

// round 8
// speedup vs baseline: 1.1902x; 1.1902x over previous
#include <cuda_runtime.h>

// CANN recurrent net as a 15-node CUDA graph with Programmatic Dependent Launch.
//   step t: y = J @ s_{t-1};  U = y/recSum_{t-1} + Iext;  s_t = (0.2 U)^2
//   (recSum_{t-1} = K*sum(s_{t-1}) recomputed deterministically by every block)
//   finalize: recSum_14, r_14 = s_14/recSum_14
//
// step_kernel: 336 blocks x 160 threads (1 warp = 1 row, 5*336 = 1680 exactly).
// J rows prefetched into registers; launch_dependents fires AFTER the prefetch
// is issued (R6 ordering: predecessor's loads stay ahead of the successor's
// flood) and BEFORE griddepcontrol.wait. 4 CTAs/SM fit at 96 regs; the wave
// uses ~2.3, leaving ~256 spare slots for early successor prefetch.

#define Nn     1680
#define NBLK   336
#define TPB    160          // 5 warps
#define NWARP  5
#define ITERS  14
#define KC     0.005f

__device__ float g_s[2][Nn];   // unnormalized s vectors, parity-buffered

__device__ __forceinline__ void pdl_wait() {
    asm volatile("griddepcontrol.wait;" ::: "memory");
}
__device__ __forceinline__ void pdl_launch_dependents() {
    asm volatile("griddepcontrol.launch_dependents;" ::: "memory");
}
__device__ __forceinline__ float4 ldcg4(const float4* p) {
    float4 v;
    asm volatile("ld.global.cg.v4.f32 {%0,%1,%2,%3}, [%4];"
                 : "=f"(v.x), "=f"(v.y), "=f"(v.z), "=f"(v.w) : "l"(p));
    return v;
}

__global__ void __launch_bounds__(TPB, 4)
step_kernel(const float* __restrict__ net_in,
            const float* __restrict__ J,
            float* __restrict__ out,
            int t)
{
    __shared__ __align__(16) float s_sm[Nn];
    __shared__ float s_part[NWARP];

    const int tid  = threadIdx.x;
    const int lane = tid & 31;
    const int wid  = tid >> 5;
    const int row  = wid * NBLK + blockIdx.x;   // exact cover: 5*336 = 1680

    // ---- prefetch (independent of predecessor): J row -> regs, Iext ----
    const float iext = __ldg(&net_in[row]);
    float4 Jr[14];
    {
        const float4* Jp = reinterpret_cast<const float4*>(J + (size_t)row * Nn);
        #pragma unroll
        for (int j = 0; j < 13; ++j) Jr[j] = __ldg(&Jp[j * 32 + lane]);
        Jr[13] = (lane < 4) ? __ldg(&Jp[416 + lane]) : make_float4(0.f,0.f,0.f,0.f);
    }

    // Gate opens only now: our prefetch loads are already queued ahead of the
    // successor's, but the successor still overlaps our dependent phase.
    pdl_launch_dependents();
    pdl_wait();                // predecessor's g_s writes now visible

    // ---- stage s_{t-1} into smem + deterministic sum (identical everywhere) ----
    const float4* src = (t == 1)
        ? reinterpret_cast<const float4*>(net_in + Nn)
        : reinterpret_cast<const float4*>(g_s[(t - 1) & 1]);
    float rsT = 0.f;
    #pragma unroll
    for (int k = 0; k < 3; ++k) {
        int i = tid + k * TPB;
        if (i < Nn / 4) {
            float4 v = (t == 1) ? __ldg(&src[i]) : ldcg4(&src[i]);
            reinterpret_cast<float4*>(s_sm)[i] = v;
            rsT += (v.x + v.y) + (v.z + v.w);
        }
    }
    #pragma unroll
    for (int o = 16; o; o >>= 1) rsT += __shfl_xor_sync(0xffffffffu, rsT, o);
    if (lane == 0) s_part[wid] = rsT;
    __syncthreads();
    const float rsum = ((s_part[0] + s_part[1]) + (s_part[2] + s_part[3])) + s_part[4];
    const float invDen = (t == 1) ? 1.0f : 1.0f / (KC * rsum);

    // ---- matvec (register J row x smem s), publish ----
    {
        const float4* s4 = reinterpret_cast<const float4*>(s_sm);
        float a0 = 0.f, a1 = 0.f;
        #pragma unroll
        for (int j = 0; j < 13; ++j) {
            float4 b = s4[j * 32 + lane];
            if (j & 1) {
                a1 = fmaf(Jr[j].x, b.x, a1); a1 = fmaf(Jr[j].y, b.y, a1);
                a1 = fmaf(Jr[j].z, b.z, a1); a1 = fmaf(Jr[j].w, b.w, a1);
            } else {
                a0 = fmaf(Jr[j].x, b.x, a0); a0 = fmaf(Jr[j].y, b.y, a0);
                a0 = fmaf(Jr[j].z, b.z, a0); a0 = fmaf(Jr[j].w, b.w, a0);
            }
        }
        if (lane < 4) {
            float4 b = s4[416 + lane];
            a1 = fmaf(Jr[13].x, b.x, a1); a1 = fmaf(Jr[13].y, b.y, a1);
            a1 = fmaf(Jr[13].z, b.z, a1); a1 = fmaf(Jr[13].w, b.w, a1);
        }
        float acc = a0 + a1;
        #pragma unroll
        for (int o = 16; o; o >>= 1) acc += __shfl_xor_sync(0xffffffffu, acc, o);
        if (lane == 0) {
            float U  = fmaf(acc, invDen, iext);
            float u2 = 0.2f * U;
            float sv = u2 * u2;
            g_s[t & 1][row] = sv;
            if (t == ITERS) out[row] = U;    // U_14
        }
    }
}

__global__ void __launch_bounds__(448)
final_kernel(float* __restrict__ out)
{
    __shared__ float s_part[14];
    const int tid = threadIdx.x, lane = tid & 31, wid = tid >> 5;

    pdl_wait();

    const float4* s4 = reinterpret_cast<const float4*>(g_s[ITERS & 1]);
    const bool has = tid < Nn / 4;     // 420 of 448 threads carry a float4
    float4 a = make_float4(0.f, 0.f, 0.f, 0.f);
    if (has) a = ldcg4(&s4[tid]);
    float v = (a.x + a.y) + (a.z + a.w);
    #pragma unroll
    for (int o = 16; o; o >>= 1) v += __shfl_xor_sync(0xffffffffu, v, o);
    if (lane == 0) s_part[wid] = v;
    __syncthreads();
    float rsum = 0.f;
    #pragma unroll
    for (int w = 0; w < 14; ++w) rsum += s_part[w];
    const float recS = KC * rsum;

    if (tid == 0) out[Nn] = recS;                       // recSum_14
    if (has) {                                          // r_14
        out[Nn + 1 + 4 * tid + 0] = a.x / recS;
        out[Nn + 1 + 4 * tid + 1] = a.y / recS;
        out[Nn + 1 + 4 * tid + 2] = a.z / recS;
        out[Nn + 1 + 4 * tid + 3] = a.w / recS;
    }
}

extern "C" void kernel_launch(void* const* d_in, const int* in_sizes, int n_in,
                              void* d_out, int out_size)
{
    const float* a = (const float*)d_in[0];
    const float* b = (const float*)d_in[1];
    const float* net_in = a;
    const float* J      = b;
    if (n_in >= 2 && in_sizes[0] > in_sizes[1]) { net_in = b; J = a; }
    float* out = (float*)d_out;

    cudaLaunchAttribute attr[1];
    attr[0].id = cudaLaunchAttributeProgrammaticStreamSerialization;
    attr[0].val.programmaticStreamSerializationAllowed = 1;

    cudaLaunchConfig_t cfg = {};
    cfg.gridDim  = dim3(NBLK, 1, 1);
    cfg.blockDim = dim3(TPB, 1, 1);
    cfg.dynamicSmemBytes = 0;
    cfg.stream = 0;            // legacy default stream (captured by harness)
    cfg.attrs = attr;
    cfg.numAttrs = 1;

    for (int t = 1; t <= ITERS; ++t)
        cudaLaunchKernelEx(&cfg, step_kernel, net_in, J, out, t);

    cudaLaunchConfig_t cfgF = cfg;
    cfgF.gridDim  = dim3(1, 1, 1);
    cfgF.blockDim = dim3(448, 1, 1);
    cudaLaunchKernelEx(&cfgF, final_kernel, out);
}

// round 9
// speedup vs baseline: 1.3014x; 1.0934x over previous
#include <cuda_runtime.h>

// CANN recurrent net as a 15-node CUDA graph with Programmatic Dependent Launch.
//   step t: y = J @ s_{t-1};  U = y/recSum_{t-1} + Iext;  s_t = (0.2 U)^2
//   finalize: recSum_14, r_14 = s_14/recSum_14
//
// R6 geometry (best measured): 296 blocks x 192 threads, launch_dependents
// AFTER the J prefetch is issued. This round shortens the dependent phase:
// recSum is computed inside the matvec loop (every warp reads all of s from
// smem anyway), deleting the per-warp partials reduce and one __syncthreads.

#define Nn     1680
#define NBLK   296
#define TPB    192          // 6 warps; 2 CTAs/SM wave, 3 fit -> 1 spare slot/SM
#define ITERS  14
#define KC     0.005f

__device__ float g_s[2][Nn];   // unnormalized s vectors, parity-buffered

__device__ __forceinline__ void pdl_wait() {
    asm volatile("griddepcontrol.wait;" ::: "memory");
}
__device__ __forceinline__ void pdl_launch_dependents() {
    asm volatile("griddepcontrol.launch_dependents;" ::: "memory");
}
__device__ __forceinline__ float4 ldcg4(const float4* p) {
    float4 v;
    asm volatile("ld.global.cg.v4.f32 {%0,%1,%2,%3}, [%4];"
                 : "=f"(v.x), "=f"(v.y), "=f"(v.z), "=f"(v.w) : "l"(p));
    return v;
}

__global__ void __launch_bounds__(TPB, 2)
step_kernel(const float* __restrict__ net_in,
            const float* __restrict__ J,
            float* __restrict__ out,
            int t)
{
    __shared__ __align__(16) float s_sm[Nn];

    const int tid  = threadIdx.x;
    const int lane = tid & 31;
    const int wid  = tid >> 5;
    const int bid  = blockIdx.x;
    const int row  = wid * NBLK + bid;       // 1680 = 5*296 + 200
    const bool active = (row < Nn);

    // ---- prefetch (independent of predecessor): J row -> regs, Iext ----
    float4 Jr[14];
    float iext = 0.f;
    if (active) {
        iext = __ldg(&net_in[row]);
        const float4* Jp = reinterpret_cast<const float4*>(J + (size_t)row * Nn);
        #pragma unroll
        for (int j = 0; j < 13; ++j) Jr[j] = __ldg(&Jp[j * 32 + lane]);
        Jr[13] = (lane < 4) ? __ldg(&Jp[416 + lane]) : make_float4(0.f,0.f,0.f,0.f);
    }

    // t=1 reads only launch-constant inputs: stage before the wait.
    if (t == 1) {
        const float4* r4 = reinterpret_cast<const float4*>(net_in + Nn);
        #pragma unroll
        for (int k = 0; k < 3; ++k) {
            int i = tid + k * TPB;
            if (i < Nn / 4) reinterpret_cast<float4*>(s_sm)[i] = __ldg(&r4[i]);
        }
    }

    // Gate opens after our loads are queued; successor overlaps our tail.
    pdl_launch_dependents();
    pdl_wait();                // predecessor's g_s writes now visible

    // ---- stage s_{t-1} into smem (t>1) ----
    if (t != 1) {
        const float4* sp = reinterpret_cast<const float4*>(g_s[(t - 1) & 1]);
        #pragma unroll
        for (int k = 0; k < 3; ++k) {
            int i = tid + k * TPB;
            if (i < Nn / 4) reinterpret_cast<float4*>(s_sm)[i] = ldcg4(&sp[i]);
        }
    }
    __syncthreads();

    // ---- matvec with fused recSum (each warp covers all of s) ----
    if (active) {
        const float4* s4 = reinterpret_cast<const float4*>(s_sm);
        float a0 = 0.f, a1 = 0.f, rs = 0.f;
        #pragma unroll
        for (int j = 0; j < 13; ++j) {
            float4 b = s4[j * 32 + lane];
            rs += (b.x + b.y) + (b.z + b.w);
            if (j & 1) {
                a1 = fmaf(Jr[j].x, b.x, a1); a1 = fmaf(Jr[j].y, b.y, a1);
                a1 = fmaf(Jr[j].z, b.z, a1); a1 = fmaf(Jr[j].w, b.w, a1);
            } else {
                a0 = fmaf(Jr[j].x, b.x, a0); a0 = fmaf(Jr[j].y, b.y, a0);
                a0 = fmaf(Jr[j].z, b.z, a0); a0 = fmaf(Jr[j].w, b.w, a0);
            }
        }
        if (lane < 4) {
            float4 b = s4[416 + lane];
            rs += (b.x + b.y) + (b.z + b.w);
            a1 = fmaf(Jr[13].x, b.x, a1); a1 = fmaf(Jr[13].y, b.y, a1);
            a1 = fmaf(Jr[13].z, b.z, a1); a1 = fmaf(Jr[13].w, b.w, a1);
        }
        float acc = a0 + a1;
        #pragma unroll
        for (int o = 16; o; o >>= 1) {
            acc += __shfl_xor_sync(0xffffffffu, acc, o);
            rs  += __shfl_xor_sync(0xffffffffu, rs,  o);
        }
        if (lane == 0) {
            const float invDen = (t == 1) ? 1.0f : 1.0f / (KC * rs);
            float U  = fmaf(acc, invDen, iext);
            float u2 = 0.2f * U;
            float sv = u2 * u2;
            g_s[t & 1][row] = sv;
            if (t == ITERS) out[row] = U;    // U_14
        }
    }
}

__global__ void __launch_bounds__(448)
final_kernel(float* __restrict__ out)
{
    __shared__ float s_part[14];
    const int tid = threadIdx.x, lane = tid & 31, wid = tid >> 5;

    pdl_wait();

    const float4* s4 = reinterpret_cast<const float4*>(g_s[ITERS & 1]);
    const bool has = tid < Nn / 4;     // 420 of 448 threads carry a float4
    float4 a = make_float4(0.f, 0.f, 0.f, 0.f);
    if (has) a = ldcg4(&s4[tid]);
    float v = (a.x + a.y) + (a.z + a.w);
    #pragma unroll
    for (int o = 16; o; o >>= 1) v += __shfl_xor_sync(0xffffffffu, v, o);
    if (lane == 0) s_part[wid] = v;
    __syncthreads();
    float rsum = 0.f;
    #pragma unroll
    for (int w = 0; w < 14; ++w) rsum += s_part[w];
    const float recS = KC * rsum;

    if (tid == 0) out[Nn] = recS;                       // recSum_14
    if (has) {                                          // r_14
        out[Nn + 1 + 4 * tid + 0] = a.x / recS;
        out[Nn + 1 + 4 * tid + 1] = a.y / recS;
        out[Nn + 1 + 4 * tid + 2] = a.z / recS;
        out[Nn + 1 + 4 * tid + 3] = a.w / recS;
    }
}

extern "C" void kernel_launch(void* const* d_in, const int* in_sizes, int n_in,
                              void* d_out, int out_size)
{
    const float* a = (const float*)d_in[0];
    const float* b = (const float*)d_in[1];
    const float* net_in = a;
    const float* J      = b;
    if (n_in >= 2 && in_sizes[0] > in_sizes[1]) { net_in = b; J = a; }
    float* out = (float*)d_out;

    cudaLaunchAttribute attr[1];
    attr[0].id = cudaLaunchAttributeProgrammaticStreamSerialization;
    attr[0].val.programmaticStreamSerializationAllowed = 1;

    cudaLaunchConfig_t cfg = {};
    cfg.gridDim  = dim3(NBLK, 1, 1);
    cfg.blockDim = dim3(TPB, 1, 1);
    cfg.dynamicSmemBytes = 0;
    cfg.stream = 0;            // legacy default stream (captured by harness)
    cfg.attrs = attr;
    cfg.numAttrs = 1;

    for (int t = 1; t <= ITERS; ++t)
        cudaLaunchKernelEx(&cfg, step_kernel, net_in, J, out, t);

    cudaLaunchConfig_t cfgF = cfg;
    cfgF.gridDim  = dim3(1, 1, 1);
    cfgF.blockDim = dim3(448, 1, 1);
    cudaLaunchKernelEx(&cfgF, final_kernel, out);
}

// round 10
// speedup vs baseline: 1.3728x; 1.0548x over previous
#include <cuda_runtime.h>

// CANN recurrent net as a 15-node CUDA graph with Programmatic Dependent Launch.
//   step t: y = J @ s_{t-1};  U = y/recSum_{t-1} + Iext;  s_t = (0.2 U)^2
//   finalize: recSum_14, r_14 = s_14/recSum_14
//
// R9 structure + one change: __launch_bounds__(192, 4) caps regs at 83 so that
// predecessor wave (2 CTAs/SM) + successor wave (2 CTAs/SM) are FULLY
// co-resident -> every successor CTA prefetches its J rows while the
// predecessor runs; the handoff cost reduces to drain + dependent phase.
// Tail of each J row held as one scalar/lane (not float4) to cut pressure.

#define Nn     1680
#define NBLK   296
#define TPB    192          // 6 warps
#define ITERS  14
#define KC     0.005f

__device__ float g_s[2][Nn];   // unnormalized s vectors, parity-buffered

__device__ __forceinline__ void pdl_wait() {
    asm volatile("griddepcontrol.wait;" ::: "memory");
}
__device__ __forceinline__ void pdl_launch_dependents() {
    asm volatile("griddepcontrol.launch_dependents;" ::: "memory");
}
__device__ __forceinline__ float4 ldcg4(const float4* p) {
    float4 v;
    asm volatile("ld.global.cg.v4.f32 {%0,%1,%2,%3}, [%4];"
                 : "=f"(v.x), "=f"(v.y), "=f"(v.z), "=f"(v.w) : "l"(p));
    return v;
}

__global__ void __launch_bounds__(TPB, 4)
step_kernel(const float* __restrict__ net_in,
            const float* __restrict__ J,
            float* __restrict__ out,
            int t)
{
    __shared__ __align__(16) float s_sm[Nn];

    const int tid  = threadIdx.x;
    const int lane = tid & 31;
    const int wid  = tid >> 5;
    const int bid  = blockIdx.x;
    const int row  = wid * NBLK + bid;       // 1680 = 5*296 + 200
    const bool active = (row < Nn);

    // ---- prefetch (independent of predecessor): J row -> regs, Iext ----
    // 1680 = 13*128 + 16: 13 float4/lane + 1 scalar for lanes 0..15.
    float4 Jr[13];
    float jtail = 0.f;
    float iext = 0.f;
    if (active) {
        iext = __ldg(&net_in[row]);
        const float* Jrow = J + (size_t)row * Nn;
        const float4* Jp = reinterpret_cast<const float4*>(Jrow);
        #pragma unroll
        for (int j = 0; j < 13; ++j) Jr[j] = __ldg(&Jp[j * 32 + lane]);
        if (lane < 16) jtail = __ldg(&Jrow[1664 + lane]);
    }

    // t=1 reads only launch-constant inputs: stage before the wait.
    if (t == 1) {
        const float4* r4 = reinterpret_cast<const float4*>(net_in + Nn);
        #pragma unroll
        for (int k = 0; k < 3; ++k) {
            int i = tid + k * TPB;
            if (i < Nn / 4) reinterpret_cast<float4*>(s_sm)[i] = __ldg(&r4[i]);
        }
    }

    // Gate opens after our loads are queued; successor overlaps our tail.
    pdl_launch_dependents();
    pdl_wait();                // predecessor's g_s writes now visible

    // ---- stage s_{t-1} into smem (t>1) ----
    if (t != 1) {
        const float4* sp = reinterpret_cast<const float4*>(g_s[(t - 1) & 1]);
        #pragma unroll
        for (int k = 0; k < 3; ++k) {
            int i = tid + k * TPB;
            if (i < Nn / 4) reinterpret_cast<float4*>(s_sm)[i] = ldcg4(&sp[i]);
        }
    }
    __syncthreads();

    // ---- matvec with fused recSum (each warp covers all of s) ----
    if (active) {
        const float4* s4 = reinterpret_cast<const float4*>(s_sm);
        float a0 = 0.f, a1 = 0.f, rs = 0.f;
        #pragma unroll
        for (int j = 0; j < 13; ++j) {
            float4 b = s4[j * 32 + lane];
            rs += (b.x + b.y) + (b.z + b.w);
            if (j & 1) {
                a1 = fmaf(Jr[j].x, b.x, a1); a1 = fmaf(Jr[j].y, b.y, a1);
                a1 = fmaf(Jr[j].z, b.z, a1); a1 = fmaf(Jr[j].w, b.w, a1);
            } else {
                a0 = fmaf(Jr[j].x, b.x, a0); a0 = fmaf(Jr[j].y, b.y, a0);
                a0 = fmaf(Jr[j].z, b.z, a0); a0 = fmaf(Jr[j].w, b.w, a0);
            }
        }
        if (lane < 16) {
            float bt = s_sm[1664 + lane];
            rs += bt;
            a1 = fmaf(jtail, bt, a1);
        }
        float acc = a0 + a1;
        #pragma unroll
        for (int o = 16; o; o >>= 1) {
            acc += __shfl_xor_sync(0xffffffffu, acc, o);
            rs  += __shfl_xor_sync(0xffffffffu, rs,  o);
        }
        if (lane == 0) {
            const float invDen = (t == 1) ? 1.0f : 1.0f / (KC * rs);
            float U  = fmaf(acc, invDen, iext);
            float u2 = 0.2f * U;
            float sv = u2 * u2;
            g_s[t & 1][row] = sv;
            if (t == ITERS) out[row] = U;    // U_14
        }
    }
}

__global__ void __launch_bounds__(448)
final_kernel(float* __restrict__ out)
{
    __shared__ float s_part[14];
    const int tid = threadIdx.x, lane = tid & 31, wid = tid >> 5;

    pdl_wait();

    const float4* s4 = reinterpret_cast<const float4*>(g_s[ITERS & 1]);
    const bool has = tid < Nn / 4;     // 420 of 448 threads carry a float4
    float4 a = make_float4(0.f, 0.f, 0.f, 0.f);
    if (has) a = ldcg4(&s4[tid]);
    float v = (a.x + a.y) + (a.z + a.w);
    #pragma unroll
    for (int o = 16; o; o >>= 1) v += __shfl_xor_sync(0xffffffffu, v, o);
    if (lane == 0) s_part[wid] = v;
    __syncthreads();
    float rsum = 0.f;
    #pragma unroll
    for (int w = 0; w < 14; ++w) rsum += s_part[w];
    const float recS = KC * rsum;

    if (tid == 0) out[Nn] = recS;                       // recSum_14
    if (has) {                                          // r_14
        out[Nn + 1 + 4 * tid + 0] = a.x / recS;
        out[Nn + 1 + 4 * tid + 1] = a.y / recS;
        out[Nn + 1 + 4 * tid + 2] = a.z / recS;
        out[Nn + 1 + 4 * tid + 3] = a.w / recS;
    }
}

extern "C" void kernel_launch(void* const* d_in, const int* in_sizes, int n_in,
                              void* d_out, int out_size)
{
    const float* a = (const float*)d_in[0];
    const float* b = (const float*)d_in[1];
    const float* net_in = a;
    const float* J      = b;
    if (n_in >= 2 && in_sizes[0] > in_sizes[1]) { net_in = b; J = a; }
    float* out = (float*)d_out;

    cudaLaunchAttribute attr[1];
    attr[0].id = cudaLaunchAttributeProgrammaticStreamSerialization;
    attr[0].val.programmaticStreamSerializationAllowed = 1;

    cudaLaunchConfig_t cfg = {};
    cfg.gridDim  = dim3(NBLK, 1, 1);
    cfg.blockDim = dim3(TPB, 1, 1);
    cfg.dynamicSmemBytes = 0;
    cfg.stream = 0;            // legacy default stream (captured by harness)
    cfg.attrs = attr;
    cfg.numAttrs = 1;

    for (int t = 1; t <= ITERS; ++t)
        cudaLaunchKernelEx(&cfg, step_kernel, net_in, J, out, t);

    cudaLaunchConfig_t cfgF = cfg;
    cfgF.gridDim  = dim3(1, 1, 1);
    cfgF.blockDim = dim3(448, 1, 1);
    cudaLaunchKernelEx(&cfgF, final_kernel, out);
}

// round 11
// speedup vs baseline: 1.5419x; 1.1232x over previous
#include <cuda_runtime.h>

// CANN recurrent net as a 15-node CUDA graph with Programmatic Dependent Launch.
//   step t: y = J @ s_{t-1};  U = y/recSum_{t-1} + Iext;  s_t = (0.2 U)^2
//   finalize: recSum_14, r_14 = s_14/recSum_14
//
// R10 structure, one variable changed: step grid 296x192 -> 148x384 (1 CTA/SM
// wave). Per-SM dependent work identical; CTA exits to track per PDL hop halve;
// launch queue halves. Regs<=84 keeps predecessor+successor waves co-resident
// so the J prefetch stays fully hidden.

#define Nn     1680
#define NBLK   148
#define TPB    384          // 12 warps; 1 CTA/SM wave, 2 fit
#define ITERS  14
#define KC     0.005f

__device__ float g_s[2][Nn];   // unnormalized s vectors, parity-buffered

__device__ __forceinline__ void pdl_wait() {
    asm volatile("griddepcontrol.wait;" ::: "memory");
}
__device__ __forceinline__ void pdl_launch_dependents() {
    asm volatile("griddepcontrol.launch_dependents;" ::: "memory");
}
__device__ __forceinline__ float4 ldcg4(const float4* p) {
    float4 v;
    asm volatile("ld.global.cg.v4.f32 {%0,%1,%2,%3}, [%4];"
                 : "=f"(v.x), "=f"(v.y), "=f"(v.z), "=f"(v.w) : "l"(p));
    return v;
}

__global__ void __launch_bounds__(TPB, 2)
step_kernel(const float* __restrict__ net_in,
            const float* __restrict__ J,
            float* __restrict__ out,
            int t)
{
    __shared__ __align__(16) float s_sm[Nn];

    const int tid  = threadIdx.x;
    const int lane = tid & 31;
    const int wid  = tid >> 5;
    const int bid  = blockIdx.x;
    const int row  = wid * NBLK + bid;       // 12*148 = 1776 slots >= 1680
    const bool active = (row < Nn);

    // ---- prefetch (independent of predecessor): J row -> regs, Iext ----
    // 1680 = 13*128 + 16: 13 float4/lane + 1 scalar for lanes 0..15.
    float4 Jr[13];
    float jtail = 0.f;
    float iext = 0.f;
    if (active) {
        iext = __ldg(&net_in[row]);
        const float* Jrow = J + (size_t)row * Nn;
        const float4* Jp = reinterpret_cast<const float4*>(Jrow);
        #pragma unroll
        for (int j = 0; j < 13; ++j) Jr[j] = __ldg(&Jp[j * 32 + lane]);
        if (lane < 16) jtail = __ldg(&Jrow[1664 + lane]);
    }

    // t=1 reads only launch-constant inputs: stage before the wait.
    if (t == 1) {
        const float4* r4 = reinterpret_cast<const float4*>(net_in + Nn);
        #pragma unroll
        for (int k = 0; k < 2; ++k) {
            int i = tid + k * TPB;
            if (i < Nn / 4) reinterpret_cast<float4*>(s_sm)[i] = __ldg(&r4[i]);
        }
    }

    // Gate opens after our loads are queued; successor overlaps our tail.
    pdl_launch_dependents();
    pdl_wait();                // predecessor's g_s writes now visible

    // ---- stage s_{t-1} into smem (t>1) ----
    if (t != 1) {
        const float4* sp = reinterpret_cast<const float4*>(g_s[(t - 1) & 1]);
        #pragma unroll
        for (int k = 0; k < 2; ++k) {
            int i = tid + k * TPB;
            if (i < Nn / 4) reinterpret_cast<float4*>(s_sm)[i] = ldcg4(&sp[i]);
        }
    }
    __syncthreads();

    // ---- matvec with fused recSum (each warp covers all of s) ----
    if (active) {
        const float4* s4 = reinterpret_cast<const float4*>(s_sm);
        float a0 = 0.f, a1 = 0.f, rs = 0.f;
        #pragma unroll
        for (int j = 0; j < 13; ++j) {
            float4 b = s4[j * 32 + lane];
            rs += (b.x + b.y) + (b.z + b.w);
            if (j & 1) {
                a1 = fmaf(Jr[j].x, b.x, a1); a1 = fmaf(Jr[j].y, b.y, a1);
                a1 = fmaf(Jr[j].z, b.z, a1); a1 = fmaf(Jr[j].w, b.w, a1);
            } else {
                a0 = fmaf(Jr[j].x, b.x, a0); a0 = fmaf(Jr[j].y, b.y, a0);
                a0 = fmaf(Jr[j].z, b.z, a0); a0 = fmaf(Jr[j].w, b.w, a0);
            }
        }
        if (lane < 16) {
            float bt = s_sm[1664 + lane];
            rs += bt;
            a1 = fmaf(jtail, bt, a1);
        }
        float acc = a0 + a1;
        #pragma unroll
        for (int o = 16; o; o >>= 1) {
            acc += __shfl_xor_sync(0xffffffffu, acc, o);
            rs  += __shfl_xor_sync(0xffffffffu, rs,  o);
        }
        if (lane == 0) {
            const float invDen = (t == 1) ? 1.0f : 1.0f / (KC * rs);
            float U  = fmaf(acc, invDen, iext);
            float u2 = 0.2f * U;
            float sv = u2 * u2;
            g_s[t & 1][row] = sv;
            if (t == ITERS) out[row] = U;    // U_14
        }
    }
}

__global__ void __launch_bounds__(448)
final_kernel(float* __restrict__ out)
{
    __shared__ float s_part[14];
    const int tid = threadIdx.x, lane = tid & 31, wid = tid >> 5;

    pdl_wait();

    const float4* s4 = reinterpret_cast<const float4*>(g_s[ITERS & 1]);
    const bool has = tid < Nn / 4;     // 420 of 448 threads carry a float4
    float4 a = make_float4(0.f, 0.f, 0.f, 0.f);
    if (has) a = ldcg4(&s4[tid]);
    float v = (a.x + a.y) + (a.z + a.w);
    #pragma unroll
    for (int o = 16; o; o >>= 1) v += __shfl_xor_sync(0xffffffffu, v, o);
    if (lane == 0) s_part[wid] = v;
    __syncthreads();
    float rsum = 0.f;
    #pragma unroll
    for (int w = 0; w < 14; ++w) rsum += s_part[w];
    const float recS = KC * rsum;

    if (tid == 0) out[Nn] = recS;                       // recSum_14
    if (has) {                                          // r_14
        out[Nn + 1 + 4 * tid + 0] = a.x / recS;
        out[Nn + 1 + 4 * tid + 1] = a.y / recS;
        out[Nn + 1 + 4 * tid + 2] = a.z / recS;
        out[Nn + 1 + 4 * tid + 3] = a.w / recS;
    }
}

extern "C" void kernel_launch(void* const* d_in, const int* in_sizes, int n_in,
                              void* d_out, int out_size)
{
    const float* a = (const float*)d_in[0];
    const float* b = (const float*)d_in[1];
    const float* net_in = a;
    const float* J      = b;
    if (n_in >= 2 && in_sizes[0] > in_sizes[1]) { net_in = b; J = a; }
    float* out = (float*)d_out;

    cudaLaunchAttribute attr[1];
    attr[0].id = cudaLaunchAttributeProgrammaticStreamSerialization;
    attr[0].val.programmaticStreamSerializationAllowed = 1;

    cudaLaunchConfig_t cfg = {};
    cfg.gridDim  = dim3(NBLK, 1, 1);
    cfg.blockDim = dim3(TPB, 1, 1);
    cfg.dynamicSmemBytes = 0;
    cfg.stream = 0;            // legacy default stream (captured by harness)
    cfg.attrs = attr;
    cfg.numAttrs = 1;

    for (int t = 1; t <= ITERS; ++t)
        cudaLaunchKernelEx(&cfg, step_kernel, net_in, J, out, t);

    cudaLaunchConfig_t cfgF = cfg;
    cfgF.gridDim  = dim3(1, 1, 1);
    cfgF.blockDim = dim3(448, 1, 1);
    cudaLaunchKernelEx(&cfgF, final_kernel, out);
}